// round 1
// baseline (speedup 1.0000x reference)
#include <cuda_runtime.h>

// ---------------- problem constants ----------------
#define BS   512
#define T_   100
#define ND   10
#define DS   6
#define INS  256
#define HID  256
#define CAT  2816        // INS*ND + HID
#define EMB  (ND*DS)     // 60
#define EMBP 64          // padded K for desc segment
#define G4   (4*HID)     // 1024
#define NOUT 266         // HID + ND
#define NP   320         // padded to 5*64
#define NSPLIT 8
#define KSPL 352         // 2816 / 8

// ---------------- device scratch (allocation-free) ----------------
__device__ float g_h[BS*HID];
__device__ float g_c[BS*HID];
__device__ float g_nxt[BS*HID];
__device__ float g_gates[BS*G4];
__device__ float g_dt[BS*EMBP];
__device__ float g_z[BS*CAT];
__device__ float g_part[NSPLIT*BS*NP];
__device__ float g_Weff[CAT*EMBP];
__device__ float g_cb[CAT];
__device__ float g_Wc[NP*CAT];
__device__ float g_bc[NP];

// ---------------- shared-memory tiled GEMM segment ----------------
// C_tile(64x64) += A[m0:m0+64, :K] * B[n0:n0+64, :K]^T  (both row-major, K contiguous)
// 256 threads, 4x4 micro-tile per thread. K % 16 == 0, pointers 16B aligned.
__device__ __forceinline__ void gemm_seg(
    const float* __restrict__ A, int lda,
    const float* __restrict__ B, int ldb,
    int K, float (&acc)[4][4],
    float* As, float* Bsm,
    int m0, int n0, int tid)
{
    const int tm = tid >> 4;        // 0..15
    const int tn = tid & 15;        // 0..15
    const int lr = tid >> 2;        // 0..63  (row within tile for loads)
    const int lk = (tid & 3) * 4;   // 0,4,8,12
    const float* Ap = A + (size_t)(m0 + lr) * lda + lk;
    const float* Bp = B + (size_t)(n0 + lr) * ldb + lk;
    for (int kt = 0; kt < K; kt += 16) {
        float4 av = *(const float4*)(Ap + kt);
        float4 bv = *(const float4*)(Bp + kt);
        // transposed store: As[k][m], Bs[k][n]
        As[(lk+0)*64 + lr] = av.x;
        As[(lk+1)*64 + lr] = av.y;
        As[(lk+2)*64 + lr] = av.z;
        As[(lk+3)*64 + lr] = av.w;
        Bsm[(lk+0)*64 + lr] = bv.x;
        Bsm[(lk+1)*64 + lr] = bv.y;
        Bsm[(lk+2)*64 + lr] = bv.z;
        Bsm[(lk+3)*64 + lr] = bv.w;
        __syncthreads();
        #pragma unroll
        for (int k = 0; k < 16; k++) {
            float4 a4 = *(const float4*)(As  + k*64 + tm*4);
            float4 b4 = *(const float4*)(Bsm + k*64 + tn*4);
            float a[4] = {a4.x, a4.y, a4.z, a4.w};
            float b[4] = {b4.x, b4.y, b4.z, b4.w};
            #pragma unroll
            for (int i = 0; i < 4; i++)
                #pragma unroll
                for (int j = 0; j < 4; j++)
                    acc[i][j] += a[i] * b[j];
        }
        __syncthreads();
    }
}

__device__ __forceinline__ float sigm(float x) { return 1.f / (1.f + __expf(-x)); }

// ---------------- per-step kernels ----------------

// gates[b,j] = nxt_prev . Wih[j] + h . Whh[j] + bih[j] + bhh[j]
__global__ void gates_kernel(const float* __restrict__ Wih,
                             const float* __restrict__ Whh,
                             const float* __restrict__ bih,
                             const float* __restrict__ bhh)
{
    __shared__ float As[16*64], Bsm[16*64];
    float acc[4][4] = {};
    const int m0 = blockIdx.x * 64, n0 = blockIdx.y * 64, tid = threadIdx.x;
    gemm_seg(g_nxt, HID, Wih, INS, INS, acc, As, Bsm, m0, n0, tid);
    gemm_seg(g_h,   HID, Whh, HID, HID, acc, As, Bsm, m0, n0, tid);
    const int tm = tid >> 4, tn = tid & 15;
    const int col = n0 + tn*4;
    float bj[4];
    #pragma unroll
    for (int j = 0; j < 4; j++) bj[j] = bih[col+j] + bhh[col+j];
    #pragma unroll
    for (int i = 0; i < 4; i++) {
        int row = m0 + tm*4 + i;
        float4 v = make_float4(acc[i][0]+bj[0], acc[i][1]+bj[1],
                               acc[i][2]+bj[2], acc[i][3]+bj[3]);
        *(float4*)(g_gates + (size_t)row*G4 + col) = v;
    }
}

// LSTM pointwise (h,c update) + stage desc_t into padded g_dt
__global__ void pointwise_kernel(const float* __restrict__ desc, int t)
{
    int gt = blockIdx.x * blockDim.x + threadIdx.x;
    if (gt < BS*HID) {
        int b = gt / HID, j = gt % HID;
        const float* g = g_gates + (size_t)b * G4;
        float ig = sigm(g[j]);
        float fg = sigm(g[j +   HID]);
        float gg = tanhf(g[j + 2*HID]);
        float og = sigm(g[j + 3*HID]);
        float c = fg * g_c[gt] + ig * gg;
        g_c[gt] = c;
        g_h[gt] = og * tanhf(c);
    } else {
        int idx = gt - BS*HID;            // < BS*EMBP
        int b = idx / EMBP, k = idx % EMBP;
        g_dt[idx] = (k < EMB) ? desc[(size_t)b * T_ * EMB + (size_t)t * EMB + k] : 0.f;
    }
}

// z[b,j] = relu( dt . Weff[j] + h . W1[j, 2560:2816] + cb[j] )
__global__ void z_kernel(const float* __restrict__ W1)
{
    __shared__ float As[16*64], Bsm[16*64];
    float acc[4][4] = {};
    const int m0 = blockIdx.x * 64, n0 = blockIdx.y * 64, tid = threadIdx.x;
    gemm_seg(g_dt, EMBP, g_Weff, EMBP, EMBP, acc, As, Bsm, m0, n0, tid);
    gemm_seg(g_h,  HID,  W1 + ND*INS, CAT, HID, acc, As, Bsm, m0, n0, tid);
    const int tm = tid >> 4, tn = tid & 15;
    const int col = n0 + tn*4;
    float bj[4];
    #pragma unroll
    for (int j = 0; j < 4; j++) bj[j] = g_cb[col+j];
    #pragma unroll
    for (int i = 0; i < 4; i++) {
        int row = m0 + tm*4 + i;
        float4 v = make_float4(fmaxf(acc[i][0]+bj[0], 0.f),
                               fmaxf(acc[i][1]+bj[1], 0.f),
                               fmaxf(acc[i][2]+bj[2], 0.f),
                               fmaxf(acc[i][3]+bj[3], 0.f));
        *(float4*)(g_z + (size_t)row*CAT + col) = v;
    }
}

// split-K partials: part[s,b,n] = z[b, sK:(s+1)K] . Wc[n, sK:(s+1)K]
__global__ void nxtpart_kernel()
{
    __shared__ float As[16*64], Bsm[16*64];
    float acc[4][4] = {};
    const int m0 = blockIdx.x * 64, n0 = blockIdx.y * 64, s = blockIdx.z;
    const int tid = threadIdx.x;
    gemm_seg(g_z + s*KSPL, CAT, g_Wc + s*KSPL, CAT, KSPL, acc, As, Bsm, m0, n0, tid);
    const int tm = tid >> 4, tn = tid & 15;
    const int col = n0 + tn*4;
    float* base = g_part + (size_t)s * BS * NP;
    #pragma unroll
    for (int i = 0; i < 4; i++) {
        int row = m0 + tm*4 + i;
        float4 v = make_float4(acc[i][0], acc[i][1], acc[i][2], acc[i][3]);
        *(float4*)(base + (size_t)row*NP + col) = v;
    }
}

// deterministic reduce + activations; writes next LSTM input and attention output
__global__ void reduce_kernel(float* __restrict__ out, int t)
{
    int gt = blockIdx.x * blockDim.x + threadIdx.x;
    if (gt >= BS * NOUT) return;
    int b = gt / NOUT, n = gt % NOUT;
    float v = g_bc[n];
    #pragma unroll
    for (int s = 0; s < NSPLIT; s++)
        v += g_part[(size_t)s * BS * NP + (size_t)b * NP + n];
    if (n < HID)
        g_nxt[(size_t)b * HID + n] = fmaxf(v, 0.f);
    else
        out[(size_t)b * T_ * ND + (size_t)t * ND + (n - HID)] = 1.f / (1.f + expf(-v));
}

// ---------------- one-time precompute ----------------

// Weff[j, n*6+d] = sum_i W1[j, n*256+i] * Wd[i, d]   (zero-padded to 64 cols)
__global__ void weff_kernel(const float* __restrict__ W1, const float* __restrict__ Wd)
{
    int gt = blockIdx.x * blockDim.x + threadIdx.x;
    if (gt >= CAT * EMBP) return;
    int j = gt / EMBP, kk = gt % EMBP;
    float v = 0.f;
    if (kk < EMB) {
        int n = kk / DS, d = kk % DS;
        const float* w1 = W1 + (size_t)j * CAT + n * INS;
        for (int i = 0; i < INS; i++) v += w1[i] * Wd[i * DS + d];
    }
    g_Weff[gt] = v;
}

// cb[j] = b1[j] + sum_{n,i} W1[j, n*256+i] * bd[i]
__global__ void cb_kernel(const float* __restrict__ W1, const float* __restrict__ b1,
                          const float* __restrict__ bd)
{
    int j = blockIdx.x * blockDim.x + threadIdx.x;
    if (j >= CAT) return;
    float v = b1[j];
    const float* w1 = W1 + (size_t)j * CAT;
    for (int n = 0; n < ND; n++)
        for (int i = 0; i < INS; i++)
            v += w1[n * INS + i] * bd[i];
    g_cb[j] = v;
}

// Wc = [W2 ; Wv ; zero-pad] with matching bias bc
__global__ void wc_kernel(const float* __restrict__ W2, const float* __restrict__ Wv,
                          const float* __restrict__ b2, const float* __restrict__ bv)
{
    int gt = blockIdx.x * blockDim.x + threadIdx.x;
    if (gt < NP * CAT) {
        int n = gt / CAT, k = gt % CAT;
        float v = 0.f;
        if (n < HID)            v = W2[(size_t)n * CAT + k];
        else if (n < NOUT)      v = Wv[(size_t)(n - HID) * CAT + k];
        g_Wc[gt] = v;
    }
    if (gt < NP)
        g_bc[gt] = (gt < HID) ? b2[gt] : ((gt < NOUT) ? bv[gt - HID] : 0.f);
}

__global__ void init_kernel()
{
    int gt = blockIdx.x * blockDim.x + threadIdx.x;
    if (gt < BS*HID) { g_h[gt] = 0.f; g_c[gt] = 0.f; g_nxt[gt] = 0.f; }
}

// ---------------- launch ----------------
extern "C" void kernel_launch(void* const* d_in, const int* in_sizes, int n_in,
                              void* d_out, int out_size)
{
    const float* desc = (const float*)d_in[0];
    const float* Wd   = (const float*)d_in[1];
    const float* bd   = (const float*)d_in[2];
    const float* W1   = (const float*)d_in[3];
    const float* b1   = (const float*)d_in[4];
    const float* W2   = (const float*)d_in[5];
    const float* b2   = (const float*)d_in[6];
    const float* Wv   = (const float*)d_in[7];
    const float* bv   = (const float*)d_in[8];
    const float* Wih  = (const float*)d_in[9];
    const float* Whh  = (const float*)d_in[10];
    const float* bih  = (const float*)d_in[11];
    const float* bhh  = (const float*)d_in[12];
    float* out = (float*)d_out;

    weff_kernel<<<(CAT*EMBP + 255)/256, 256>>>(W1, Wd);
    cb_kernel  <<<(CAT + 255)/256, 256>>>(W1, b1, bd);
    wc_kernel  <<<(NP*CAT + 255)/256, 256>>>(W2, Wv, b2, bv);
    init_kernel<<<(BS*HID + 255)/256, 256>>>();

    for (int t = 0; t < T_; t++) {
        gates_kernel   <<<dim3(BS/64, G4/64), 256>>>(Wih, Whh, bih, bhh);
        pointwise_kernel<<<(BS*HID + BS*EMBP)/256, 256>>>(desc, t);
        z_kernel       <<<dim3(BS/64, CAT/64), 256>>>(W1);
        nxtpart_kernel <<<dim3(BS/64, NP/64, NSPLIT), 256>>>();
        reduce_kernel  <<<(BS*NOUT + 255)/256, 256>>>(out, t);
    }
}